// round 12
// baseline (speedup 1.0000x reference)
#include <cuda_runtime.h>
#include <cuda_bf16.h>
#include <math.h>

// Problem constants
#define B_    32
#define C_    256
#define O_    256
#define HH    56
#define WW    56
#define KTOT  2304            // C*9
#define NKP   1152            // KTOT/2 k-pairs

typedef unsigned int u32;

// ---------------- device scratch (no dynamic allocation allowed) ------------
__device__ float g_pooled[B_ * C_];                 // [b][c]
__device__ float g_kern[B_ * C_ * 4];               // [b][c*4+ch]
__device__ float g_wT[KTOT * O_];                   // [k][o]
__device__ u32   g_dynw[(size_t)B_ * NKP * O_];     // [b][kp][o] f16x2 {lo=2kp, hi=2kp+1}

// ---------------- helpers ---------------------------------------------------
__device__ __forceinline__ u32 smaddr(const void* p) {
    return (u32)__cvta_generic_to_shared(p);
}
__device__ __forceinline__ void cp16(u32 dst, const void* src) {
    asm volatile("cp.async.cg.shared.global [%0], [%1], 16;" :: "r"(dst), "l"(src));
}
__device__ __forceinline__ void cp_commit() { asm volatile("cp.async.commit_group;"); }
template <int N> __device__ __forceinline__ void cp_wait() {
    asm volatile("cp.async.wait_group %0;" :: "n"(N));
}
// pack {lo, hi} floats -> f16x2 register (cvt.rn.f16x2.f32 d, a, b => d={lo=b, hi=a})
__device__ __forceinline__ u32 packh2(float hi, float lo) {
    u32 d;
    asm("cvt.rn.f16x2.f32 %0, %1, %2;" : "=r"(d) : "f"(hi), "f"(lo));
    return d;
}
__device__ __forceinline__ void mma_f16(float* c, const u32* a, u32 b0, u32 b1) {
    asm volatile(
        "mma.sync.aligned.m16n8k16.row.col.f32.f16.f16.f32 "
        "{%0,%1,%2,%3}, {%4,%5,%6,%7}, {%8,%9}, {%0,%1,%2,%3};"
        : "+f"(c[0]), "+f"(c[1]), "+f"(c[2]), "+f"(c[3])
        : "r"(a[0]), "r"(a[1]), "r"(a[2]), "r"(a[3]), "r"(b0), "r"(b1));
}

// ---------------- K1: global average pool ------------------------------------
__global__ void pool_kernel(const float* __restrict__ x) {
    int bc = blockIdx.x;
    const float* p = x + (size_t)bc * (HH * WW);
    float s = 0.f;
    for (int i = threadIdx.x; i < HH * WW; i += 256) s += p[i];
    __shared__ float red[256];
    red[threadIdx.x] = s;
    __syncthreads();
    for (int st = 128; st > 0; st >>= 1) {
        if (threadIdx.x < st) red[threadIdx.x] += red[threadIdx.x + st];
        __syncthreads();
    }
    if (threadIdx.x == 0) g_pooled[bc] = red[0] * (1.f / (HH * WW));
}

// ---------------- K2: fc1(relu) + fc2 fused ----------------------------------
__global__ void fc_kernel(const float* __restrict__ fc1w,
                          const float* __restrict__ fc2w,
                          const float* __restrict__ fc2b) {
    int b = blockIdx.x, t = threadIdx.x;
    __shared__ float sp[C_], sh[C_];
    sp[t] = g_pooled[b * C_ + t];
    __syncthreads();
    float d = 0.f;
    const float* w1 = fc1w + t * C_;
    #pragma unroll 8
    for (int k = 0; k < C_; k++) d += sp[k] * w1[k];
    sh[t] = fmaxf(d, 0.f);
    __syncthreads();
    #pragma unroll
    for (int r = 0; r < 4; r++) {
        int j = r * 256 + t;
        const float* w2 = fc2w + j * C_;
        float d2 = fc2b[j];
        #pragma unroll 8
        for (int k = 0; k < C_; k++) d2 += sh[k] * w2[k];
        g_kern[b * (C_ * 4) + j] = d2;
    }
}

// ---------------- K2.5: transpose weight [o][c][ij] -> [k][o] ----------------
__global__ void wt_kernel(const float* __restrict__ w) {
    int e = blockIdx.x * 256 + threadIdx.x;        // < 589824
    int o = e / KTOT;
    int rem = e - o * KTOT;                         // k
    g_wT[(size_t)rem * O_ + o] = w[e];
}

// ---------------- K3: dynamic weights -> packed fp16 pairs [b][kp][o] --------
__global__ void dynw_kernel(const float* __restrict__ cog) {
    int b = blockIdx.x >> 5;
    int g = blockIdx.x & 31;                        // kp-group of 36
    int o = threadIdx.x;                            // 256 threads
    __shared__ float cogs[36 * 256];                // [ch*9+ij][o]
    for (int e = o; e < 36 * 256; e += 256) {
        int kk = e >> 8, oo = e & 255;
        cogs[e] = cog[oo * 36 + kk];
    }
    __syncthreads();
    const float* kern = g_kern + b * (C_ * 4);
    for (int t = 0; t < 36; t++) {
        int kp = g * 36 + t;
        int k0 = 2 * kp, k1 = k0 + 1;
        int c0 = k0 / 9, ij0 = k0 - c0 * 9;
        int c1 = k1 / 9, ij1 = k1 - c1 * 9;
        float s0 = kern[c0 * 4 + 0] * cogs[(0 + ij0) * 256 + o]
                 + kern[c0 * 4 + 1] * cogs[(9 + ij0) * 256 + o]
                 + kern[c0 * 4 + 2] * cogs[(18 + ij0) * 256 + o]
                 + kern[c0 * 4 + 3] * cogs[(27 + ij0) * 256 + o];
        float s1 = kern[c1 * 4 + 0] * cogs[(0 + ij1) * 256 + o]
                 + kern[c1 * 4 + 1] * cogs[(9 + ij1) * 256 + o]
                 + kern[c1 * 4 + 2] * cogs[(18 + ij1) * 256 + o]
                 + kern[c1 * 4 + 3] * cogs[(27 + ij1) * 256 + o];
        float v0 = (1.f / (1.f + expf(-s0))) * g_wT[(size_t)k0 * O_ + o];
        float v1 = (1.f / (1.f + expf(-s1))) * g_wT[(size_t)k1 * O_ + o];
        g_dynw[((size_t)b * NKP + kp) * O_ + o] = packh2(v1, v0);
    }
}

// ---------------- K5: implicit-GEMM conv, fp16 m16n8k16 mma.sync -------------
// Block: 64 o x 4 rows x 56 px, 256 thr (8 warps), 2 blocks/SM.
// Warp: wm = wid&1 -> 32 o (2 m16 tiles), wn = wid>>1 -> 1 row (7 n8 tiles).
// K: 16 chunks of 144 (16 channels), 9 k16-steps each; double-buffered cp.async.
#define NCH      16
#define KPC      72            // k-pairs per chunk
#define APITCH   72            // words per kp row (64 data + 8 pad) -> conflict-free
#define A_WORDS  (KPC * APITCH)            // 5184
#define XS_BASE  A_WORDS
#define XS_WORDS (16 * 6 * 64)             // 6144 floats
#define STAGE_W  (A_WORDS + XS_WORDS)      // 11328 words
#define CONV_SMEM (2 * STAGE_W * 4)        // 90624 B

extern __shared__ u32 smw[];

__device__ __forceinline__ void stage_chunk(const float* __restrict__ x,
                                            int b, int o0, int r0x,
                                            int t, int tid) {
    const int buf = t & 1;
    u32* st = smw + buf * STAGE_W;
    const u32 sbase = smaddr(st);
    // A: 72 kp rows x 64 words (f16x2), 16 cp16 per row
    const u32* asrc = g_dynw + ((size_t)b * NKP + t * KPC) * O_ + o0;
    #pragma unroll
    for (int e = tid; e < KPC * 16; e += 256) {
        int kp = e >> 4;
        int q  = e & 15;
        cp16(sbase + ((kp * APITCH + q * 4) << 2), asrc + (size_t)kp * O_ + q * 4);
    }
    // x: 16 c x 6 rows x 56 interior cols (14 cp16/row); halo/OOB persistent zeros
    const int c_lo = t * 16;
    for (int e = tid; e < 16 * 6 * 14; e += 256) {
        int cc = e / 84;
        int r2 = e - cc * 84;
        int rr = r2 / 14;
        int f  = r2 - rr * 14;
        int gr = r0x + rr;
        if ((unsigned)gr < HH)
            cp16(sbase + ((XS_BASE + cc * 384 + rr * 64 + 4 + f * 4) << 2),
                 x + (((size_t)b * C_ + c_lo + cc) * HH + gr) * WW + f * 4);
    }
}

__global__ __launch_bounds__(256, 2)
void conv_kernel(const float* __restrict__ x, float* __restrict__ out) {
    const int rg = blockIdx.x;                 // 0..13 (4-row group)
    const int ot = blockIdx.y;                 // 0..3  (64-o tile)
    const int b  = blockIdx.z;                 // 0..31
    const int r0 = rg * 4;
    const int o0 = ot * 64;
    const int r0x = r0 - 1;

    const int tid  = threadIdx.x;
    const int wid  = tid >> 5;
    const int lane = tid & 31;
    const int wm = wid & 1;                    // 32-o half
    const int wn = wid >> 1;                   // row in group (0..3)
    const int grp = lane >> 2;                 // 0..7
    const int qid = lane & 3;                  // 0..3

    // zero both stage buffers once (persistent xs halo zeros)
    for (int e = tid; e < 2 * STAGE_W; e += 256) smw[e] = 0u;
    __syncthreads();

    float acc[2][7][4];
    #pragma unroll
    for (int mt = 0; mt < 2; mt++)
        #pragma unroll
        for (int nt = 0; nt < 7; nt++)
            #pragma unroll
            for (int r = 0; r < 4; r++) acc[mt][nt][r] = 0.f;

    stage_chunk(x, b, o0, r0x, 0, tid);
    cp_commit();

    for (int it = 0; it < NCH; it++) {
        const int buf = it & 1;
        if (it + 1 < NCH) {
            stage_chunk(x, b, o0, r0x, it + 1, tid);
            cp_commit();
            cp_wait<1>();
        } else {
            cp_wait<0>();
        }
        __syncthreads();

        const u32* sA = smw + buf * STAGE_W;
        const float* xs = (const float*)(sA + XS_BASE);

        #pragma unroll
        for (int s = 0; s < 9; s++) {
            // ---- A fragments: kp rows 8s+qid and +4, o = wm*32 + mt*16 + grp(+8)
            const u32* pa = sA + (8 * s + qid) * APITCH + wm * 32 + grp;
            u32 a[2][4];
            #pragma unroll
            for (int mt = 0; mt < 2; mt++) {
                const u32* pm = pa + mt * 16;
                a[mt][0] = pm[0];
                a[mt][1] = pm[8];
                a[mt][2] = pm[4 * APITCH];
                a[mt][3] = pm[4 * APITCH + 8];
            }
            // ---- B offsets for k-locals e0, e0+1, e0+8, e0+9
            const int e0 = 16 * s + 2 * qid;
            const int ca = e0 / 9,      ija = e0 - ca * 9;
            const int cb = (e0 + 1) / 9, ijb = (e0 + 1) - cb * 9;
            const int cc = (e0 + 8) / 9, ijc = (e0 + 8) - cc * 9;
            const int cd = (e0 + 9) / 9, ijd = (e0 + 9) - cd * 9;
            const int offa = ca * 384 + (wn + ija / 3) * 64 + 3 + ija % 3;
            const int offb = cb * 384 + (wn + ijb / 3) * 64 + 3 + ijb % 3;
            const int offc = cc * 384 + (wn + ijc / 3) * 64 + 3 + ijc % 3;
            const int offd = cd * 384 + (wn + ijd / 3) * 64 + 3 + ijd % 3;
            #pragma unroll
            for (int nt = 0; nt < 7; nt++) {
                const int n = nt * 8 + grp;
                u32 b0 = packh2(xs[offb + n], xs[offa + n]);
                u32 b1 = packh2(xs[offd + n], xs[offc + n]);
                mma_f16(acc[0][nt], a[0], b0, b1);
                mma_f16(acc[1][nt], a[1], b0, b1);
            }
        }
        __syncthreads();
    }

    // ---- epilogue ----
    const int row = r0 + wn;
    #pragma unroll
    for (int mt = 0; mt < 2; mt++) {
        const int o_lo = o0 + wm * 32 + mt * 16 + grp;
        float* p0 = out + (((size_t)b * O_ + o_lo) * HH + row) * WW;
        float* p1 = p0 + (size_t)8 * HH * WW;          // o_lo + 8
        #pragma unroll
        for (int nt = 0; nt < 7; nt++) {
            const int col = nt * 8 + qid * 2;
            *(float2*)(p0 + col) = make_float2(acc[mt][nt][0], acc[mt][nt][1]);
            *(float2*)(p1 + col) = make_float2(acc[mt][nt][2], acc[mt][nt][3]);
        }
    }
}

// ---------------- launch ------------------------------------------------------
extern "C" void kernel_launch(void* const* d_in, const int* in_sizes, int n_in,
                              void* d_out, int out_size) {
    const float* x    = (const float*)d_in[0];   // [32,256,56,56]
    const float* fc1w = (const float*)d_in[1];   // [256,256]
    const float* fc2w = (const float*)d_in[2];   // [1024,256]
    const float* fc2b = (const float*)d_in[3];   // [1024]
    const float* cog  = (const float*)d_in[4];   // [256,4,3,3]
    const float* w    = (const float*)d_in[5];   // [256,256,3,3]
    float* out = (float*)d_out;                  // [32,256,56,56]

    cudaFuncSetAttribute(conv_kernel,
                         cudaFuncAttributeMaxDynamicSharedMemorySize, CONV_SMEM);

    pool_kernel<<<B_ * C_, 256>>>(x);
    fc_kernel<<<B_, 256>>>(fc1w, fc2w, fc2b);
    wt_kernel<<<(O_ * C_ * 9) / 256, 256>>>(w);
    dynw_kernel<<<B_ * 32, 256>>>(cog);
    dim3 grid(14, 4, 32);
    conv_kernel<<<grid, 256, CONV_SMEM>>>(x, out);
}

// round 13
// speedup vs baseline: 1.5712x; 1.5712x over previous
#include <cuda_runtime.h>
#include <cuda_bf16.h>
#include <math.h>

// Problem constants
#define B_  32
#define C_  256
#define O_  256
#define HH  56
#define WW  56
#define NT  784          // 28*28 Winograd output tiles (2x2 each)
#define TW  28

typedef unsigned int u32;

// ---------------- device scratch (no dynamic allocation allowed) ------------
__device__ float g_pooled[B_ * C_];                  // [b][c]
__device__ float g_kern[B_ * C_ * 4];                // [b][c*4+ch]
__device__ float g_wT[C_ * 9 * O_];                  // [c*9+ij][o]
__device__ u32   g_U[(size_t)B_ * 16 * 128 * O_];    // [b][t][cp][o]  f16x2 over c-pair
__device__ u32   g_V[(size_t)B_ * 16 * 128 * NT];    // [b][t][cp][n]  f16x2 over c-pair
__device__ float g_M[(size_t)B_ * 16 * O_ * NT];     // [b][t][o][n]   fp32

// ---------------- helpers ---------------------------------------------------
__device__ __forceinline__ u32 smaddr(const void* p) {
    return (u32)__cvta_generic_to_shared(p);
}
__device__ __forceinline__ void cp16(u32 dst, const void* src) {
    asm volatile("cp.async.cg.shared.global [%0], [%1], 16;" :: "r"(dst), "l"(src));
}
__device__ __forceinline__ void cp_commit() { asm volatile("cp.async.commit_group;"); }
template <int N> __device__ __forceinline__ void cp_wait() {
    asm volatile("cp.async.wait_group %0;" :: "n"(N));
}
// pack {lo, hi} -> f16x2 (cvt.rn.f16x2.f32 d, a, b => d = {lo=b, hi=a})
__device__ __forceinline__ u32 packh2(float hi, float lo) {
    u32 d;
    asm("cvt.rn.f16x2.f32 %0, %1, %2;" : "=r"(d) : "f"(hi), "f"(lo));
    return d;
}
__device__ __forceinline__ void mma_f16(float* c, const u32* a, u32 b0, u32 b1) {
    asm volatile(
        "mma.sync.aligned.m16n8k16.row.col.f32.f16.f16.f32 "
        "{%0,%1,%2,%3}, {%4,%5,%6,%7}, {%8,%9}, {%0,%1,%2,%3};"
        : "+f"(c[0]), "+f"(c[1]), "+f"(c[2]), "+f"(c[3])
        : "r"(a[0]), "r"(a[1]), "r"(a[2]), "r"(a[3]), "r"(b0), "r"(b1));
}

// ---------------- K1: global average pool ------------------------------------
__global__ void pool_kernel(const float* __restrict__ x) {
    int bc = blockIdx.x;
    const float* p = x + (size_t)bc * (HH * WW);
    float s = 0.f;
    for (int i = threadIdx.x; i < HH * WW; i += 256) s += p[i];
    __shared__ float red[256];
    red[threadIdx.x] = s;
    __syncthreads();
    for (int st = 128; st > 0; st >>= 1) {
        if (threadIdx.x < st) red[threadIdx.x] += red[threadIdx.x + st];
        __syncthreads();
    }
    if (threadIdx.x == 0) g_pooled[bc] = red[0] * (1.f / (HH * WW));
}

// ---------------- K2: fc1(relu) + fc2 fused ----------------------------------
__global__ void fc_kernel(const float* __restrict__ fc1w,
                          const float* __restrict__ fc2w,
                          const float* __restrict__ fc2b) {
    int b = blockIdx.x, t = threadIdx.x;
    __shared__ float sp[C_], sh[C_];
    sp[t] = g_pooled[b * C_ + t];
    __syncthreads();
    float d = 0.f;
    const float* w1 = fc1w + t * C_;
    #pragma unroll 8
    for (int k = 0; k < C_; k++) d += sp[k] * w1[k];
    sh[t] = fmaxf(d, 0.f);
    __syncthreads();
    #pragma unroll
    for (int r = 0; r < 4; r++) {
        int j = r * 256 + t;
        const float* w2 = fc2w + j * C_;
        float d2 = fc2b[j];
        #pragma unroll 8
        for (int k = 0; k < C_; k++) d2 += sh[k] * w2[k];
        g_kern[b * (C_ * 4) + j] = d2;
    }
}

// ---------------- K2.5: transpose weight [o][c][ij] -> [c*9+ij][o] -----------
__global__ void wt_kernel(const float* __restrict__ w) {
    int e = blockIdx.x * 256 + threadIdx.x;
    int o = e / (C_ * 9);
    int rem = e - o * (C_ * 9);
    g_wT[(size_t)rem * O_ + o] = w[e];
}

// ---------------- K3: dyn weight + Winograd U transform ----------------------
// g[b,o,c,3x3] = sigmoid(cw)*w  ->  U = G g G^T (4x4) -> f16 pairs [b][t][cp][o]
__global__ void uwino_kernel(const float* __restrict__ cog) {
    const int cp = blockIdx.x;        // 0..127
    const int b  = blockIdx.y;
    const int o  = threadIdx.x;       // 256
    __shared__ float cogs[36 * 256];  // [ch*9+ij][o]
    __shared__ float ks[1024];
    for (int e = o; e < 36 * 256; e += 256) {
        int kk = e >> 8, oo = e & 255;
        cogs[e] = cog[oo * 36 + kk];
    }
    for (int e = o; e < 1024; e += 256) ks[e] = g_kern[b * 1024 + e];
    __syncthreads();

    float U[2][16];
    #pragma unroll
    for (int h = 0; h < 2; h++) {
        const int c = 2 * cp + h;
        float g[9];
        #pragma unroll
        for (int ij = 0; ij < 9; ij++) {
            float s = ks[c * 4 + 0] * cogs[(0 + ij) * 256 + o]
                    + ks[c * 4 + 1] * cogs[(9 + ij) * 256 + o]
                    + ks[c * 4 + 2] * cogs[(18 + ij) * 256 + o]
                    + ks[c * 4 + 3] * cogs[(27 + ij) * 256 + o];
            g[ij] = (1.f / (1.f + expf(-s))) * g_wT[(size_t)(c * 9 + ij) * O_ + o];
        }
        float q[4][3];
        #pragma unroll
        for (int j = 0; j < 3; j++) {
            q[0][j] = g[0 * 3 + j];
            q[1][j] = 0.5f * (g[0 * 3 + j] + g[1 * 3 + j] + g[2 * 3 + j]);
            q[2][j] = 0.5f * (g[0 * 3 + j] - g[1 * 3 + j] + g[2 * 3 + j]);
            q[3][j] = g[2 * 3 + j];
        }
        #pragma unroll
        for (int i = 0; i < 4; i++) {
            U[h][i * 4 + 0] = q[i][0];
            U[h][i * 4 + 1] = 0.5f * (q[i][0] + q[i][1] + q[i][2]);
            U[h][i * 4 + 2] = 0.5f * (q[i][0] - q[i][1] + q[i][2]);
            U[h][i * 4 + 3] = q[i][2];
        }
    }
    u32* dst = g_U + ((size_t)b * 16) * (128 * 256) + cp * 256 + o;
    #pragma unroll
    for (int t = 0; t < 16; t++)
        dst[(size_t)t * (128 * 256)] = packh2(U[1][t], U[0][t]);
}

// ---------------- K4: Winograd input transform V = B^T d B --------------------
__global__ void vwino_kernel(const float* __restrict__ x) {
    const int n  = blockIdx.x * 256 + threadIdx.x;
    const int cp = blockIdx.y;
    const int b  = blockIdx.z;
    if (n >= NT) return;
    const int ty = n / TW, tx = n - ty * TW;
    const int r0 = 2 * ty - 1, q0 = 2 * tx - 1;

    float V[2][16];
    #pragma unroll
    for (int h = 0; h < 2; h++) {
        const int c = 2 * cp + h;
        const float* xp = x + ((size_t)b * C_ + c) * (HH * WW);
        float d[4][4];
        #pragma unroll
        for (int r = 0; r < 4; r++) {
            const int gr = r0 + r;
            #pragma unroll
            for (int j = 0; j < 4; j++) {
                const int gc = q0 + j;
                d[r][j] = ((unsigned)gr < HH && (unsigned)gc < WW)
                        ? xp[gr * WW + gc] : 0.f;
            }
        }
        float z[4][4];
        #pragma unroll
        for (int j = 0; j < 4; j++) {
            z[0][j] = d[0][j] - d[2][j];
            z[1][j] = d[1][j] + d[2][j];
            z[2][j] = d[2][j] - d[1][j];
            z[3][j] = d[1][j] - d[3][j];
        }
        #pragma unroll
        for (int i = 0; i < 4; i++) {
            V[h][i * 4 + 0] = z[i][0] - z[i][2];
            V[h][i * 4 + 1] = z[i][1] + z[i][2];
            V[h][i * 4 + 2] = z[i][2] - z[i][1];
            V[h][i * 4 + 3] = z[i][1] - z[i][3];
        }
    }
    u32* dst = g_V + ((size_t)b * 16) * (128 * NT) + cp * NT + n;
    #pragma unroll
    for (int t = 0; t < 16; t++)
        dst[(size_t)t * (128 * NT)] = packh2(V[1][t], V[0][t]);
}

// ---------------- K5: batched Winograd GEMM (fp16 m16n8k16) -------------------
// Per (b, t): M[256 o][784 n] = sum_cp U[cp][o] * V[cp][n], K = 128 pairs.
// Block: 128 o x 112 n, 8 warps (warp 32 o x 56 n), K chunks of 16 kp.
#define AP 136                 // A smem pitch (words): 136 % 32 = 8 -> conflict-free
#define VP 120                 // V smem pitch: 120 % 32 = 24 -> conflict-free
#define SA_W (16 * AP)         // 2176
#define SV_W (16 * VP)         // 1920
#define STG_W (SA_W + SV_W)    // 4096 words = 16 KB per stage

__global__ __launch_bounds__(256, 2)
void wgemm_kernel() {
    const int gx = blockIdx.x;             // 0..13
    const int nb = gx >> 1, mo = gx & 1;
    const int t = blockIdx.y, b = blockIdx.z;
    const int o0 = mo * 128, n0 = nb * 112;

    const int tid  = threadIdx.x;
    const int wid  = tid >> 5, lane = tid & 31;
    const int wm = wid & 3;                // 32-o quarter
    const int wn = wid >> 2;               // 56-n half
    const int grp = lane >> 2, qid = lane & 3;

    __shared__ u32 sm[2 * STG_W];

    const u32* aG = g_U + ((size_t)(b * 16 + t)) * (128 * 256) + o0;
    const u32* vG = g_V + ((size_t)(b * 16 + t)) * (128 * NT) + n0;

    float acc[2][7][4];
    #pragma unroll
    for (int mt = 0; mt < 2; mt++)
        #pragma unroll
        for (int nt = 0; nt < 7; nt++)
            #pragma unroll
            for (int r = 0; r < 4; r++) acc[mt][nt][r] = 0.f;

    // stage chunk 0
    {
        u32* s = sm;
        for (int e = tid; e < 512; e += 256) {
            int kp = e >> 5, q = e & 31;
            cp16(smaddr(s + kp * AP + q * 4), aG + kp * 256 + q * 4);
        }
        for (int e = tid; e < 448; e += 256) {
            int kp = e / 28, q = e - kp * 28;
            cp16(smaddr(s + SA_W + kp * VP + q * 4), vG + (size_t)kp * NT + q * 4);
        }
    }
    cp_commit();

    for (int it = 0; it < 8; it++) {
        if (it + 1 < 8) {
            u32* s = sm + ((it + 1) & 1) * STG_W;
            const u32* aS = aG + (it + 1) * 16 * 256;
            const u32* vS = vG + (size_t)(it + 1) * 16 * NT;
            for (int e = tid; e < 512; e += 256) {
                int kp = e >> 5, q = e & 31;
                cp16(smaddr(s + kp * AP + q * 4), aS + kp * 256 + q * 4);
            }
            for (int e = tid; e < 448; e += 256) {
                int kp = e / 28, q = e - kp * 28;
                cp16(smaddr(s + SA_W + kp * VP + q * 4), vS + (size_t)kp * NT + q * 4);
            }
            cp_commit();
            cp_wait<1>();
        } else {
            cp_wait<0>();
        }
        __syncthreads();

        const u32* sA = sm + (it & 1) * STG_W;
        const u32* sV = sA + SA_W;

        #pragma unroll
        for (int s = 0; s < 2; s++) {
            const u32* pa = sA + (8 * s + qid) * AP + wm * 32 + grp;
            u32 a[2][4];
            #pragma unroll
            for (int mt = 0; mt < 2; mt++) {
                const u32* pm = pa + mt * 16;
                a[mt][0] = pm[0];
                a[mt][1] = pm[8];
                a[mt][2] = pm[4 * AP];
                a[mt][3] = pm[4 * AP + 8];
            }
            const u32* pv = sV + (8 * s + qid) * VP + wn * 56 + grp;
            #pragma unroll
            for (int nt = 0; nt < 7; nt++) {
                u32 b0 = pv[nt * 8];
                u32 b1 = pv[4 * VP + nt * 8];
                mma_f16(acc[0][nt], a[0], b0, b1);
                mma_f16(acc[1][nt], a[1], b0, b1);
            }
        }
        __syncthreads();
    }

    // epilogue -> g_M fp32
    #pragma unroll
    for (int mt = 0; mt < 2; mt++) {
        const int row = o0 + wm * 32 + mt * 16 + grp;
        float* p0 = g_M + ((size_t)(b * 16 + t) * 256 + row) * NT + n0 + wn * 56;
        float* p1 = p0 + 8 * NT;
        #pragma unroll
        for (int nt = 0; nt < 7; nt++) {
            const int col = nt * 8 + 2 * qid;
            *(float2*)(p0 + col) = make_float2(acc[mt][nt][0], acc[mt][nt][1]);
            *(float2*)(p1 + col) = make_float2(acc[mt][nt][2], acc[mt][nt][3]);
        }
    }
}

// ---------------- K6: output transform Y = A^T M A ----------------------------
__global__ void yout_kernel(float* __restrict__ out) {
    const int n = blockIdx.x * 256 + threadIdx.x;
    const int o = blockIdx.y;
    const int b = blockIdx.z;
    if (n >= NT) return;
    const float* mp = g_M + ((size_t)(b * 16) * 256 + o) * NT + n;
    float m[16];
    #pragma unroll
    for (int t = 0; t < 16; t++) m[t] = mp[(size_t)t * (256 * NT)];
    float s0[4], s1[4];
    #pragma unroll
    for (int j = 0; j < 4; j++) {
        s0[j] = m[0 + j] + m[4 + j] + m[8 + j];
        s1[j] = m[4 + j] - m[8 + j] - m[12 + j];
    }
    const float y00 = s0[0] + s0[1] + s0[2];
    const float y01 = s0[1] - s0[2] - s0[3];
    const float y10 = s1[0] + s1[1] + s1[2];
    const float y11 = s1[1] - s1[2] - s1[3];
    const int ty = n / TW, tx = n - ty * TW;
    float* op = out + ((size_t)(b * O_ + o) * HH + 2 * ty) * WW + 2 * tx;
    *(float2*)op = make_float2(y00, y01);
    *(float2*)(op + WW) = make_float2(y10, y11);
}

// ---------------- launch ------------------------------------------------------
extern "C" void kernel_launch(void* const* d_in, const int* in_sizes, int n_in,
                              void* d_out, int out_size) {
    const float* x    = (const float*)d_in[0];   // [32,256,56,56]
    const float* fc1w = (const float*)d_in[1];   // [256,256]
    const float* fc2w = (const float*)d_in[2];   // [1024,256]
    const float* fc2b = (const float*)d_in[3];   // [1024]
    const float* cog  = (const float*)d_in[4];   // [256,4,3,3]
    const float* w    = (const float*)d_in[5];   // [256,256,3,3]
    float* out = (float*)d_out;                  // [32,256,56,56]

    pool_kernel<<<B_ * C_, 256>>>(x);
    fc_kernel<<<B_, 256>>>(fc1w, fc2w, fc2b);
    wt_kernel<<<(O_ * C_ * 9) / 256, 256>>>(w);
    uwino_kernel<<<dim3(128, 32), 256>>>(cog);
    vwino_kernel<<<dim3(4, 128, 32), 256>>>(x);
    wgemm_kernel<<<dim3(14, 16, 32), 256>>>();
    yout_kernel<<<dim3(4, 256, 32), 256>>>(out);
}